// round 1
// baseline (speedup 1.0000x reference)
#include <cuda_runtime.h>

#define N_NODES 50000
#define N_EDGES 800000
#define D_FEAT  64
#define UNITS   64

// Scratch accumulator (alloc-free rule: __device__ global array)
__device__ float g_agg[N_NODES * D_FEAT];

// ---------------------------------------------------------------------------
// Kernel 1: zero the accumulator (float4 stores)
// ---------------------------------------------------------------------------
__global__ void zero_agg_kernel() {
    int i = blockIdx.x * blockDim.x + threadIdx.x;
    const int n4 = N_NODES * D_FEAT / 4;
    if (i < n4) {
        reinterpret_cast<float4*>(g_agg)[i] = make_float4(0.f, 0.f, 0.f, 0.f);
    }
}

// ---------------------------------------------------------------------------
// Kernel 2: SpMM scatter-add.
// One thread per (edge, 16-byte chunk): 16 threads cover one 64-float row.
// Consecutive threads read consecutive float4s of the same embedding row
// (256B coalesced). Scatter uses red.global.add.v4.f32 (sm_90+): no-return
// vector reduction, 4x fewer atomic ops than scalar atomicAdd.
// ---------------------------------------------------------------------------
__global__ void spmm_kernel(const float* __restrict__ emb,
                            const int*   __restrict__ src,
                            const int*   __restrict__ dst,
                            const float* __restrict__ w) {
    long idx = (long)blockIdx.x * blockDim.x + threadIdx.x;
    const long total = (long)N_EDGES * (D_FEAT / 4);
    if (idx >= total) return;

    int e = (int)(idx >> 4);   // edge id
    int c = (int)(idx & 15);   // float4 chunk within the row

    int   s  = __ldg(src + e);
    int   d  = __ldg(dst + e);
    float we = __ldg(w + e);

    float4 v = __ldg(reinterpret_cast<const float4*>(emb + (long)s * D_FEAT) + c);
    v.x *= we; v.y *= we; v.z *= we; v.w *= we;

    float* out = g_agg + (long)d * D_FEAT + c * 4;
    asm volatile("red.global.add.v4.f32 [%0], {%1, %2, %3, %4};"
                 :: "l"(out), "f"(v.x), "f"(v.y), "f"(v.z), "f"(v.w)
                 : "memory");
}

// ---------------------------------------------------------------------------
// Kernel 3: dense [N,64] @ [64,64] + ReLU.
// 8 warps/block, one warp per output row. Weight matrix cached in smem.
// Each lane holds 2 elements of the A row in registers; broadcast via shfl.
// Each lane produces output columns {lane, lane+32}. smem accesses are
// conflict-free (lane indexes the contiguous column dimension).
// ---------------------------------------------------------------------------
__global__ void gemm_relu_kernel(const float* __restrict__ kern,
                                 float* __restrict__ out) {
    __shared__ float sK[UNITS * D_FEAT];  // [k][j], row stride 64

    int tid = threadIdx.x;
    // cooperative load of the 64x64 weight matrix (16 KB) as float4
    #pragma unroll
    for (int i = tid; i < D_FEAT * UNITS / 4; i += 256) {
        reinterpret_cast<float4*>(sK)[i] =
            __ldg(reinterpret_cast<const float4*>(kern) + i);
    }
    __syncthreads();

    int warp = tid >> 5;
    int lane = tid & 31;
    int row  = blockIdx.x * 8 + warp;
    if (row >= N_NODES) return;

    const float* a = g_agg + (long)row * D_FEAT;
    float a0 = a[lane];
    float a1 = a[lane + 32];

    float acc0 = 0.f, acc1 = 0.f;
    #pragma unroll
    for (int k = 0; k < 32; k++) {
        float av = __shfl_sync(0xffffffff, a0, k);
        acc0 = fmaf(av, sK[k * UNITS + lane], acc0);
        acc1 = fmaf(av, sK[k * UNITS + lane + 32], acc1);
    }
    #pragma unroll
    for (int k = 0; k < 32; k++) {
        float av = __shfl_sync(0xffffffff, a1, k);
        acc0 = fmaf(av, sK[(k + 32) * UNITS + lane], acc0);
        acc1 = fmaf(av, sK[(k + 32) * UNITS + lane + 32], acc1);
    }

    out[(long)row * UNITS + lane]      = fmaxf(acc0, 0.f);
    out[(long)row * UNITS + lane + 32] = fmaxf(acc1, 0.f);
}

// ---------------------------------------------------------------------------
// Launch
// ---------------------------------------------------------------------------
extern "C" void kernel_launch(void* const* d_in, const int* in_sizes, int n_in,
                              void* d_out, int out_size) {
    const float* emb  = (const float*)d_in[0];
    const int*   src  = (const int*)  d_in[1];
    const int*   dst  = (const int*)  d_in[2];
    const float* w    = (const float*)d_in[3];
    const float* kern = (const float*)d_in[4];
    float* out        = (float*)d_out;

    // 1) zero accumulator
    {
        int n4 = N_NODES * D_FEAT / 4;
        zero_agg_kernel<<<(n4 + 255) / 256, 256>>>();
    }
    // 2) SpMM scatter-add
    {
        long total = (long)N_EDGES * (D_FEAT / 4);  // 12.8M threads
        int blocks = (int)((total + 255) / 256);
        spmm_kernel<<<blocks, 256>>>(emb, src, dst, w);
    }
    // 3) GEMM + ReLU
    {
        int blocks = (N_NODES + 7) / 8;
        gemm_relu_kernel<<<blocks, 256>>>(kern, out);
    }
}